// round 7
// baseline (speedup 1.0000x reference)
#include <cuda_runtime.h>
#include <cuda_bf16.h>
#include <cstdint>

// Problem constants
#define Z   16
#define Y   384
#define X   384
#define CX  385            // cells per axis (padded unfold output)
#define TX  32             // cell tile width  (x)
#define TY  8              // cell tile height (y)
#define NTX 13             // ceil(385/32)
#define NTY 49             // ceil(385/8)
#define FP  ((TY+1)*(TX+1))  // 297 footprint voxels per slice
#define SSTR (TX+4)        // smem row stride (36)
#define EPSF 1e-12f

// Accumulators: zero at load; reset by the last block each launch so the
// invariant holds across graph replays.
__device__ double g_acc[3];   // [0]=sum pw*la, [1]=sum la+pa, [2]=sum interior bce
__device__ unsigned g_ticket;

// Single fused kernel: sigmoid + unfold + codes + dice/bce reduction.
// Block = 256 threads = 32x8 cell tile; marches z through 18 padded slices
// with a double-buffered smem slice pipeline.
__global__ void __launch_bounds__(256) k_fused(const float* __restrict__ pred,
                                               const int*   __restrict__ lab,
                                               const float* __restrict__ area,
                                               float*       __restrict__ out) {
    __shared__ float          sW[2][TY + 1][SSTR];
    __shared__ unsigned short sC[2][TY + 1][SSTR];
    __shared__ float sA[256];
    __shared__ float rN[8], rD[8], rB[8];

    const int tid = threadIdx.x;
    sA[tid] = area[tid];

    const int lx = tid & 31, ly = tid >> 5;
    const int vx0 = blockIdx.x * TX;   // padded voxel x of footprint col 0
    const int vy0 = blockIdx.y * TY;   // padded voxel y of footprint row 0
    const bool valid = (vy0 + ly < CX) && (vx0 + lx < CX);

    // Load padded slice pz (0..17) into smem buffer b.
    auto load_slice = [&](int pz, int b) {
        if (pz == 0 || pz == Z + 1) {
#pragma unroll
            for (int i = tid; i < FP; i += 256) {
                int row = i / (TX + 1), col = i - row * (TX + 1);
                sW[b][row][col] = 0.0f;
                sC[b][row][col] = 0;
            }
        } else {
            for (int i = tid; i < FP; i += 256) {
                int row = i / (TX + 1), col = i - row * (TX + 1);
                int vy = vy0 + row, vx = vx0 + col;   // padded coords (0..385)
                float w = 0.0f;
                unsigned short c = 0;
                if (vy >= 1 && vy <= Y && vx >= 1 && vx <= X) {
                    int gi = ((pz - 1) * Y + (vy - 1)) * X + (vx - 1);
                    float p = pred[gi];
                    int   l = lab[gi];
                    float s = __fdividef(1.0f, 1.0f + __expf(-p));
                    w = l ? (s - 1.0f) : s;                 // (s - l); sign encodes l
                    c = (unsigned short)((l ? 1u : 0u) | ((s > 0.5f) ? 0x100u : 0u));
                }
                sW[b][row][col] = w;
                sC[b][row][col] = c;
            }
        }
    };

    float accN = 0.0f, accD = 0.0f, accB = 0.0f;

    load_slice(0, 0);
    for (int zp = 0; zp < Z + 1; zp++) {
        load_slice(zp + 1, (zp + 1) & 1);
        __syncthreads();

        if (valid) {
            const int pb = zp & 1, cb = (zp + 1) & 1;
            float wa0 = sW[pb][ly][lx],     wa1 = sW[pb][ly][lx + 1];
            float wa2 = sW[pb][ly + 1][lx], wa3 = sW[pb][ly + 1][lx + 1];
            float wb0 = sW[cb][ly][lx],     wb1 = sW[cb][ly][lx + 1];
            float wb2 = sW[cb][ly + 1][lx], wb3 = sW[cb][ly + 1][lx + 1];

            // corner k = dz*4 + dy*2 + dx; label bits land in 0..7, pred bits in 8..15
            unsigned m = (unsigned)sC[pb][ly][lx]
                       | ((unsigned)sC[pb][ly][lx + 1]     << 1)
                       | ((unsigned)sC[pb][ly + 1][lx]     << 2)
                       | ((unsigned)sC[pb][ly + 1][lx + 1] << 3)
                       | ((unsigned)sC[cb][ly][lx]         << 4)
                       | ((unsigned)sC[cb][ly][lx + 1]     << 5)
                       | ((unsigned)sC[cb][ly + 1][lx]     << 6)
                       | ((unsigned)sC[cb][ly + 1][lx + 1] << 7);
            int code  = (int)(m & 255u);          // label corner byte
            int pcode = (int)((m >> 8) & 255u);   // pred corner byte (per-bit threshold)

            float d2 = fmaf(wa0, wa0, fmaf(wa1, wa1, fmaf(wa2, wa2,
                       fmaf(wa3, wa3, fmaf(wb0, wb0, fmaf(wb1, wb1,
                       fmaf(wb2, wb2, wb3 * wb3)))))));
            float la = sA[code];
            float pa = sA[pcode];
            accN = fmaf(fmaf(d2, -0.125f, 1.0f), la, accN);   // pw * label_area
            accD += la + pa;

            if (code == 0 || code == 255) {
                // per-corner bce: -log(max(1-|w|, EPS)) covers both label cases
                float b = __logf(fmaxf(1.0f - fabsf(wa0), EPSF))
                        + __logf(fmaxf(1.0f - fabsf(wa1), EPSF))
                        + __logf(fmaxf(1.0f - fabsf(wa2), EPSF))
                        + __logf(fmaxf(1.0f - fabsf(wa3), EPSF))
                        + __logf(fmaxf(1.0f - fabsf(wb0), EPSF))
                        + __logf(fmaxf(1.0f - fabsf(wb1), EPSF))
                        + __logf(fmaxf(1.0f - fabsf(wb2), EPSF))
                        + __logf(fmaxf(1.0f - fabsf(wb3), EPSF));
                accB -= b;
            }
        }
        __syncthreads();   // protect prev buffer before next load overwrites it
    }

    // block reduction -> double atomics -> last-block finalize
#pragma unroll
    for (int o = 16; o > 0; o >>= 1) {
        accN += __shfl_down_sync(0xffffffffu, accN, o);
        accD += __shfl_down_sync(0xffffffffu, accD, o);
        accB += __shfl_down_sync(0xffffffffu, accB, o);
    }
    int wid = tid >> 5, lane = tid & 31;
    if (lane == 0) { rN[wid] = accN; rD[wid] = accD; rB[wid] = accB; }
    __syncthreads();
    if (tid == 0) {
        float n = 0.0f, d = 0.0f, b = 0.0f;
#pragma unroll
        for (int i = 0; i < 8; i++) { n += rN[i]; d += rD[i]; b += rB[i]; }
        atomicAdd(&g_acc[0], (double)n);
        atomicAdd(&g_acc[1], (double)d);
        atomicAdd(&g_acc[2], (double)b);
        __threadfence();
        unsigned tk = atomicAdd(&g_ticket, 1u);
        if (tk == (unsigned)(NTX * NTY - 1)) {
            __threadfence();
            double num = 2.0 * g_acc[0];
            double den = g_acc[1];
            double vol = g_acc[2] / (8.0 * (double)CX * (double)CX);
            double dice = 1.0 - (num + 1e-3) / (den + 1e-3);
            out[0] = (float)(dice + vol);
            g_acc[0] = 0.0; g_acc[1] = 0.0; g_acc[2] = 0.0;
            g_ticket = 0u;
            __threadfence();
        }
    }
}

extern "C" void kernel_launch(void* const* d_in, const int* in_sizes, int n_in,
                              void* d_out, int out_size) {
    const float* pred = (const float*)d_in[0];
    const int*   lab  = (const int*)d_in[1];
    const float* area = (const float*)d_in[2];
    (void)in_sizes; (void)n_in; (void)out_size;

    dim3 grid(NTX, NTY);
    k_fused<<<grid, 256>>>(pred, lab, area, (float*)d_out);
}

// round 8
// speedup vs baseline: 1.1515x; 1.1515x over previous
#include <cuda_runtime.h>
#include <cuda_bf16.h>
#include <cstdint>

// Problem constants
#define Z   16
#define Y   384
#define X   384
#define SL  (Y*X)          // 147456 voxels per slice
#define CX  385            // cells per axis (padded unfold output)
#define TX  32             // cell tile width  (x)
#define TY  8              // cell tile height (y)
#define NTX 13             // ceil(385/32)
#define NTY 49             // ceil(385/8)
#define FP  ((TY+1)*(TX+1))  // 297 footprint voxels per slice
#define SSTR 36            // smem row stride (33 data + pad)
#define EPSF 1e-12f

// Accumulators: zero at load; reset by the last block each launch so the
// invariant holds across graph replays.
__device__ double g_acc[3];   // [0]=sum pw*la, [1]=sum la+pa, [2]=sum interior bce
__device__ unsigned g_ticket;

// Pack one voxel: sign bit = label, mantissa LSB = (s > 0.5), magnitude = |s - l|.
__device__ __forceinline__ unsigned packv(float p, int l) {
    float u = __expf(-p);
    float s = __fdividef(1.0f, 1.0f + u);
    float aw = l ? (1.0f - s) : s;                 // |w|, w = s - l
    unsigned b = __float_as_uint(aw);
    return (b & 0x7FFFFFFEu) | ((unsigned)l << 31) | ((s > 0.5f) ? 1u : 0u);
}

__global__ void __launch_bounds__(256) k_fused(const float* __restrict__ pred,
                                               const int*   __restrict__ lab,
                                               const float* __restrict__ area,
                                               float*       __restrict__ out) {
    __shared__ unsigned sS[TY + 1][SSTR];   // single packed slice buffer
    __shared__ float sA[256];
    __shared__ float rN[8], rD[8], rB[8];

    const int tid = threadIdx.x;
    sA[tid] = area[tid];

    const int lx = tid & 31, ly = tid >> 5;
    const int vx0 = blockIdx.x * TX;
    const int vy0 = blockIdx.y * TY;
    const bool valid = (vy0 + ly < CX) && (vx0 + lx < CX);

    // Footprint items (fixed per thread across all z): item0 = tid, item1 = tid+256.
    const int r0 = tid / 33, c0 = tid - r0 * 33;
    const int vyA = vy0 + r0, vxA = vx0 + c0;            // padded coords
    const bool gA = (vyA >= 1 && vyA <= Y) && (vxA >= 1 && vxA <= X);
    const int giA = gA ? ((vyA - 1) * X + (vxA - 1)) : 0;
    const int soA = r0 * SSTR + c0;

    const int it1 = tid + 256;
    const bool has1 = it1 < FP;
    const int r1 = it1 / 33, c1 = it1 - r1 * 33;
    const int vyB = vy0 + r1, vxB = vx0 + c1;
    const bool gB = has1 && (vyB >= 1 && vyB <= Y) && (vxB >= 1 && vxB <= X);
    const int giB = gB ? ((vyB - 1) * X + (vxB - 1)) : 0;
    const int soB = has1 ? (r1 * SSTR + c1) : soA;       // harmless dup if !has1

    unsigned* sFlat = &sS[0][0];

    // Prologue: load + pack padded slice pz=1 (real slice 0).
    unsigned pkA = 0, pkB = 0;
    if (gA) pkA = packv(__ldg(pred + giA), __ldg(lab + giA));
    if (gB) pkB = packv(__ldg(pred + giB), __ldg(lab + giB));

    float accN = 0.0f, accD = 0.0f, accB = 0.0f;

    // Prev-slice carry (padded slice 0 = zeros).
    float cw0 = 0.0f, cw1 = 0.0f, cw2 = 0.0f, cw3 = 0.0f;
    unsigned nLp = 0, nPp = 0;
    float sqp = 0.0f;

    for (int zp = 0; zp < Z + 1; zp++) {
        // Store packed slice zp+1 into the (now free) buffer.
        sFlat[soA] = pkA;
        if (has1) sFlat[soB] = pkB;
        __syncthreads();

        // Prefetch slice zp+2 (real iff zp <= 14; zp==15 -> zero slice 17).
        float rpA = 0.0f, rpB = 0.0f;
        int   rlA = 0,    rlB = 0;
        const bool pf = (zp <= 14);
        if (pf) {
            const int base = (zp + 1) * SL;
            if (gA) { rpA = __ldg(pred + base + giA); rlA = __ldg(lab + base + giA); }
            if (gB) { rpB = __ldg(pred + base + giB); rlB = __ldg(lab + base + giB); }
        }

        // Compute this pair's cell: prev from registers, cur from smem.
        if (valid) {
            unsigned u0 = sS[ly][lx],     u1 = sS[ly][lx + 1];
            unsigned u2 = sS[ly + 1][lx], u3 = sS[ly + 1][lx + 1];

            unsigned nL = (u0 >> 31) | ((u1 >> 31) << 1) | ((u2 >> 31) << 2) | ((u3 >> 31) << 3);
            unsigned nP = (u0 & 1u) | ((u1 & 1u) << 1) | ((u2 & 1u) << 2) | ((u3 & 1u) << 3);

            float w0 = __uint_as_float(u0), w1 = __uint_as_float(u1);
            float w2 = __uint_as_float(u2), w3 = __uint_as_float(u3);
            float sq = fmaf(w0, w0, fmaf(w1, w1, fmaf(w2, w2, w3 * w3)));

            int code  = (int)(nLp | (nL << 4));   // label corner byte
            int pcode = (int)(nPp | (nP << 4));   // pred corner byte
            float d2 = sqp + sq;

            float la = sA[code];
            float pa = sA[pcode];
            accN = fmaf(fmaf(d2, -0.125f, 1.0f), la, accN);   // pw * label_area
            accD += la + pa;

            if (code == 0 || code == 255) {
                float b = __logf(fmaxf(1.0f - fabsf(cw0), EPSF))
                        + __logf(fmaxf(1.0f - fabsf(cw1), EPSF))
                        + __logf(fmaxf(1.0f - fabsf(cw2), EPSF))
                        + __logf(fmaxf(1.0f - fabsf(cw3), EPSF))
                        + __logf(fmaxf(1.0f - fabsf(w0), EPSF))
                        + __logf(fmaxf(1.0f - fabsf(w1), EPSF))
                        + __logf(fmaxf(1.0f - fabsf(w2), EPSF))
                        + __logf(fmaxf(1.0f - fabsf(w3), EPSF));
                accB -= b;
            }

            cw0 = w0; cw1 = w1; cw2 = w2; cw3 = w3;
            nLp = nL; nPp = nP; sqp = sq;
        }

        // Pack prefetched slice (register-only; LDG has had compute to land).
        pkA = (pf && gA) ? packv(rpA, rlA) : 0u;
        pkB = (pf && gB) ? packv(rpB, rlB) : 0u;

        __syncthreads();   // all smem reads done before next iteration's STS
    }

    // Block reduction -> double atomics -> last-block finalize.
#pragma unroll
    for (int o = 16; o > 0; o >>= 1) {
        accN += __shfl_down_sync(0xffffffffu, accN, o);
        accD += __shfl_down_sync(0xffffffffu, accD, o);
        accB += __shfl_down_sync(0xffffffffu, accB, o);
    }
    int wid = tid >> 5, lane = tid & 31;
    if (lane == 0) { rN[wid] = accN; rD[wid] = accD; rB[wid] = accB; }
    __syncthreads();
    if (tid == 0) {
        float n = 0.0f, d = 0.0f, b = 0.0f;
#pragma unroll
        for (int i = 0; i < 8; i++) { n += rN[i]; d += rD[i]; b += rB[i]; }
        atomicAdd(&g_acc[0], (double)n);
        atomicAdd(&g_acc[1], (double)d);
        atomicAdd(&g_acc[2], (double)b);
        __threadfence();
        unsigned tk = atomicAdd(&g_ticket, 1u);
        if (tk == (unsigned)(NTX * NTY - 1)) {
            __threadfence();
            double num = 2.0 * g_acc[0];
            double den = g_acc[1];
            double vol = g_acc[2] / (8.0 * (double)CX * (double)CX);
            double dice = 1.0 - (num + 1e-3) / (den + 1e-3);
            out[0] = (float)(dice + vol);
            g_acc[0] = 0.0; g_acc[1] = 0.0; g_acc[2] = 0.0;
            g_ticket = 0u;
            __threadfence();
        }
    }
}

extern "C" void kernel_launch(void* const* d_in, const int* in_sizes, int n_in,
                              void* d_out, int out_size) {
    const float* pred = (const float*)d_in[0];
    const int*   lab  = (const int*)d_in[1];
    const float* area = (const float*)d_in[2];
    (void)in_sizes; (void)n_in; (void)out_size;

    dim3 grid(NTX, NTY);
    k_fused<<<grid, 256>>>(pred, lab, area, (float*)d_out);
}